// round 1
// baseline (speedup 1.0000x reference)
#include <cuda_runtime.h>
#include <cuda_bf16.h>
#include <cstdint>

#define NN 40000
#define EE 640000
#define BB 256

// ---------------- scratch (device globals; no allocation) ----------------
__device__ float g_agg[NN * 128];
__device__ float g_cnt[NN];
__device__ float g_inv[NN];
__device__ float g_h1[NN * 128];
__device__ float g_h2[NN * 128];
__device__ float g_e[NN];
__device__ float g_A[BB * 384];      // cols 0:256 = q_star, cols 256:384 = h
__device__ float g_c[BB * 128];
__device__ float g_gates[BB * 512];
__device__ float g_emax[BB];
__device__ float g_den[BB];
__device__ float g_rraw[BB * 128];
__device__ float g_Wl[512 * 384];    // packed [Wih | Whh]
__device__ float g_bl[512];          // bih + bhh
__device__ float g_s1[128], g_t1[128], g_s2[128], g_t2[128];

// ---------------- helpers ----------------
__device__ __forceinline__ void redAdd4(float* p, float4 v) {
    asm volatile("red.global.add.v4.f32 [%0], {%1,%2,%3,%4};"
                 :: "l"(p), "f"(v.x), "f"(v.y), "f"(v.z), "f"(v.w) : "memory");
}

__device__ __forceinline__ void atomicMaxF(float* addr, float v) {
    if (v >= 0.f) atomicMax((int*)addr, __float_as_int(v));
    else          atomicMin((unsigned int*)addr, __float_as_uint(v));
}

__device__ __forceinline__ float sigmoidf(float x) { return 1.f / (1.f + expf(-x)); }

// ---------------- tiny kernels ----------------
__global__ void k_zero(float* p, int n) {
    int i = blockIdx.x * blockDim.x + threadIdx.x;
    if (i < n) p[i] = 0.f;
}

__global__ void k_bnprep(const float* g1, const float* be1, const float* rm1, const float* rv1,
                         const float* g2, const float* be2, const float* rm2, const float* rv2) {
    int i = threadIdx.x;
    if (i < 128) {
        float s = g1[i] * rsqrtf(rv1[i] + 1e-5f);
        g_s1[i] = s; g_t1[i] = be1[i] - rm1[i] * s;
    } else {
        int j = i - 128;
        float s = g2[j] * rsqrtf(rv2[j] + 1e-5f);
        g_s2[j] = s; g_t2[j] = be2[j] - rm2[j] * s;
    }
}

__global__ void k_pack(const float* Wih, const float* Whh, const float* bih, const float* bhh) {
    int i = blockIdx.x * blockDim.x + threadIdx.x;
    if (i < 512 * 384) {
        int r = i / 384, k = i % 384;
        g_Wl[i] = (k < 256) ? Wih[r * 256 + k] : Whh[r * 128 + (k - 256)];
    }
    if (i < 512) g_bl[i] = bih[i] + bhh[i];
}

__global__ void k_invcnt() {
    int i = blockIdx.x * blockDim.x + threadIdx.x;
    if (i < NN) g_inv[i] = 1.f / fmaxf(g_cnt[i], 1.f);
}

// ---------------- edge scatter: warp per edge, vector red ----------------
__global__ void k_scatter(const float* __restrict__ feat, const int* __restrict__ ei,
                          float* __restrict__ agg, float* __restrict__ cnt, int doCnt) {
    int gt = blockIdx.x * blockDim.x + threadIdx.x;
    int w = gt >> 5;
    if (w >= EE) return;
    int lane = gt & 31;
    int s = __ldg(ei + w);
    int d = __ldg(ei + EE + w);
    float4 v = *(const float4*)(feat + (size_t)s * 128 + lane * 4);
    redAdd4(agg + (size_t)d * 128 + lane * 4, v);
    if (doCnt && lane == 0) atomicAdd(cnt + d, 1.0f);
}

// ---------------- fused layer GEMM: relu(((agg*inv | x) @ (Wl|Wr)^T + bl)*s + t) ----------------
// BM=64, BN=128, BK=16, 256 threads, each thread 4x8 outputs.
__global__ __launch_bounds__(256) void k_layer_gemm(
    const float* __restrict__ Aagg, const float* __restrict__ Ax,
    const float* __restrict__ inv,
    const float* __restrict__ Wl, const float* __restrict__ Wr,
    const float* __restrict__ bl, const float* __restrict__ s, const float* __restrict__ t,
    float* __restrict__ out) {
    __shared__ float As[16][65];
    __shared__ float Ws[16][132];
    int tid = threadIdx.x;
    int m0 = blockIdx.x * 64;
    int lr = tid >> 2;              // 0..63
    int lk = (tid & 3) * 4;         // 0,4,8,12
    int ty = tid >> 4, tx = tid & 15;
    int ty4 = ty * 4, tx8 = tx * 8;
    int row = m0 + lr;
    float invr = inv[row];

    float acc[4][8];
#pragma unroll
    for (int i = 0; i < 4; i++)
#pragma unroll
        for (int j = 0; j < 8; j++) acc[i][j] = 0.f;

#pragma unroll
    for (int half = 0; half < 2; half++) {
        const float* Ab = half ? Ax : Aagg;
        const float* Wb = half ? Wr : Wl;
        float sc = half ? 1.f : invr;
        for (int k0 = 0; k0 < 128; k0 += 16) {
            float4 av = *(const float4*)(Ab + (size_t)row * 128 + k0 + lk);
            av.x *= sc; av.y *= sc; av.z *= sc; av.w *= sc;
            float4 w0 = *(const float4*)(Wb + (size_t)lr * 128 + k0 + lk);
            float4 w1 = *(const float4*)(Wb + (size_t)(lr + 64) * 128 + k0 + lk);
            As[lk + 0][lr] = av.x; As[lk + 1][lr] = av.y; As[lk + 2][lr] = av.z; As[lk + 3][lr] = av.w;
            Ws[lk + 0][lr] = w0.x; Ws[lk + 1][lr] = w0.y; Ws[lk + 2][lr] = w0.z; Ws[lk + 3][lr] = w0.w;
            Ws[lk + 0][64 + lr] = w1.x; Ws[lk + 1][64 + lr] = w1.y; Ws[lk + 2][64 + lr] = w1.z; Ws[lk + 3][64 + lr] = w1.w;
            __syncthreads();
#pragma unroll
            for (int k = 0; k < 16; k++) {
                float a0 = As[k][ty4], a1 = As[k][ty4 + 1], a2 = As[k][ty4 + 2], a3 = As[k][ty4 + 3];
                float4 wa = *(float4*)&Ws[k][tx8];
                float4 wb = *(float4*)&Ws[k][tx8 + 4];
                acc[0][0] += a0 * wa.x; acc[0][1] += a0 * wa.y; acc[0][2] += a0 * wa.z; acc[0][3] += a0 * wa.w;
                acc[0][4] += a0 * wb.x; acc[0][5] += a0 * wb.y; acc[0][6] += a0 * wb.z; acc[0][7] += a0 * wb.w;
                acc[1][0] += a1 * wa.x; acc[1][1] += a1 * wa.y; acc[1][2] += a1 * wa.z; acc[1][3] += a1 * wa.w;
                acc[1][4] += a1 * wb.x; acc[1][5] += a1 * wb.y; acc[1][6] += a1 * wb.z; acc[1][7] += a1 * wb.w;
                acc[2][0] += a2 * wa.x; acc[2][1] += a2 * wa.y; acc[2][2] += a2 * wa.z; acc[2][3] += a2 * wa.w;
                acc[2][4] += a2 * wb.x; acc[2][5] += a2 * wb.y; acc[2][6] += a2 * wb.z; acc[2][7] += a2 * wb.w;
                acc[3][0] += a3 * wa.x; acc[3][1] += a3 * wa.y; acc[3][2] += a3 * wa.z; acc[3][3] += a3 * wa.w;
                acc[3][4] += a3 * wb.x; acc[3][5] += a3 * wb.y; acc[3][6] += a3 * wb.z; acc[3][7] += a3 * wb.w;
            }
            __syncthreads();
        }
    }
#pragma unroll
    for (int i = 0; i < 4; i++) {
        int m = m0 + ty4 + i;
#pragma unroll
        for (int j = 0; j < 8; j++) {
            int n = tx8 + j;
            float v = acc[i][j] + bl[n];
            v = fmaf(v, s[n], t[n]);
            out[(size_t)m * 128 + n] = fmaxf(v, 0.f);
        }
    }
}

// ---------------- generic small GEMM: out = A @ W^T + bias ----------------
__global__ __launch_bounds__(256) void k_gemm(const float* __restrict__ A, int lda,
                                              const float* __restrict__ W, int ldw,
                                              const float* __restrict__ bias,
                                              float* __restrict__ out, int ldo, int K) {
    __shared__ float As[16][65];
    __shared__ float Ws[16][132];
    int tid = threadIdx.x;
    int m0 = blockIdx.x * 64, n0 = blockIdx.y * 128;
    int lr = tid >> 2;
    int lk = (tid & 3) * 4;
    int ty = tid >> 4, tx = tid & 15;
    int ty4 = ty * 4, tx8 = tx * 8;

    float acc[4][8];
#pragma unroll
    for (int i = 0; i < 4; i++)
#pragma unroll
        for (int j = 0; j < 8; j++) acc[i][j] = 0.f;

    for (int k0 = 0; k0 < K; k0 += 16) {
        float4 av = *(const float4*)(A + (size_t)(m0 + lr) * lda + k0 + lk);
        float4 w0 = *(const float4*)(W + (size_t)(n0 + lr) * ldw + k0 + lk);
        float4 w1 = *(const float4*)(W + (size_t)(n0 + lr + 64) * ldw + k0 + lk);
        As[lk + 0][lr] = av.x; As[lk + 1][lr] = av.y; As[lk + 2][lr] = av.z; As[lk + 3][lr] = av.w;
        Ws[lk + 0][lr] = w0.x; Ws[lk + 1][lr] = w0.y; Ws[lk + 2][lr] = w0.z; Ws[lk + 3][lr] = w0.w;
        Ws[lk + 0][64 + lr] = w1.x; Ws[lk + 1][64 + lr] = w1.y; Ws[lk + 2][64 + lr] = w1.z; Ws[lk + 3][64 + lr] = w1.w;
        __syncthreads();
#pragma unroll
        for (int k = 0; k < 16; k++) {
            float a0 = As[k][ty4], a1 = As[k][ty4 + 1], a2 = As[k][ty4 + 2], a3 = As[k][ty4 + 3];
            float4 wa = *(float4*)&Ws[k][tx8];
            float4 wb = *(float4*)&Ws[k][tx8 + 4];
            acc[0][0] += a0 * wa.x; acc[0][1] += a0 * wa.y; acc[0][2] += a0 * wa.z; acc[0][3] += a0 * wa.w;
            acc[0][4] += a0 * wb.x; acc[0][5] += a0 * wb.y; acc[0][6] += a0 * wb.z; acc[0][7] += a0 * wb.w;
            acc[1][0] += a1 * wa.x; acc[1][1] += a1 * wa.y; acc[1][2] += a1 * wa.z; acc[1][3] += a1 * wa.w;
            acc[1][4] += a1 * wb.x; acc[1][5] += a1 * wb.y; acc[1][6] += a1 * wb.z; acc[1][7] += a1 * wb.w;
            acc[2][0] += a2 * wa.x; acc[2][1] += a2 * wa.y; acc[2][2] += a2 * wa.z; acc[2][3] += a2 * wa.w;
            acc[2][4] += a2 * wb.x; acc[2][5] += a2 * wb.y; acc[2][6] += a2 * wb.z; acc[2][7] += a2 * wb.w;
            acc[3][0] += a3 * wa.x; acc[3][1] += a3 * wa.y; acc[3][2] += a3 * wa.z; acc[3][3] += a3 * wa.w;
            acc[3][4] += a3 * wb.x; acc[3][5] += a3 * wb.y; acc[3][6] += a3 * wb.z; acc[3][7] += a3 * wb.w;
        }
        __syncthreads();
    }
#pragma unroll
    for (int i = 0; i < 4; i++) {
        int m = m0 + ty4 + i;
#pragma unroll
        for (int j = 0; j < 8; j++) {
            int n = n0 + tx8 + j;
            out[(size_t)m * ldo + n] = acc[i][j] + bias[n];
        }
    }
}

// ---------------- set2set pointwise ----------------
__global__ void k_lstm() {
    int g = blockIdx.x, d = threadIdx.x;
    const float* gt = g_gates + g * 512;
    float ig = gt[d], fg = gt[128 + d], gg = gt[256 + d], og = gt[384 + d];
    float c0 = g_c[g * 128 + d];
    float cn = sigmoidf(fg) * c0 + sigmoidf(ig) * tanhf(gg);
    float hn = sigmoidf(og) * tanhf(cn);
    g_c[g * 128 + d] = cn;
    g_A[g * 384 + 256 + d] = hn;
    g_rraw[g * 128 + d] = 0.f;
    if (d == 0) { g_emax[g] = __int_as_float(0xff800000U); g_den[g] = 0.f; }
}

__global__ void k_attn_e(const int* __restrict__ batch) {
    int gt = blockIdx.x * blockDim.x + threadIdx.x;
    int n = gt >> 5;
    if (n >= NN) return;
    int lane = gt & 31;
    int b = __ldg(batch + n);
    float4 hv = *(const float4*)(g_h2 + (size_t)n * 128 + lane * 4);
    float4 qv = *(const float4*)(g_A + (size_t)b * 384 + 256 + lane * 4);
    float p = hv.x * qv.x + hv.y * qv.y + hv.z * qv.z + hv.w * qv.w;
#pragma unroll
    for (int o = 16; o > 0; o >>= 1) p += __shfl_xor_sync(0xffffffffu, p, o);
    if (lane == 0) { g_e[n] = p; atomicMaxF(&g_emax[b], p); }
}

__global__ void k_attn_r(const int* __restrict__ batch) {
    int gt = blockIdx.x * blockDim.x + threadIdx.x;
    int n = gt >> 5;
    if (n >= NN) return;
    int lane = gt & 31;
    int b = __ldg(batch + n);
    float a = expf(g_e[n] - g_emax[b]);
    float4 hv = *(const float4*)(g_h2 + (size_t)n * 128 + lane * 4);
    float4 v; v.x = a * hv.x; v.y = a * hv.y; v.z = a * hv.z; v.w = a * hv.w;
    redAdd4(g_rraw + (size_t)b * 128 + lane * 4, v);
    if (lane == 0) atomicAdd(&g_den[b], a);
}

__global__ void k_qstar() {
    int g = blockIdx.x, d = threadIdx.x;
    float den = g_den[g];
    float r = (den > 0.f) ? g_rraw[g * 128 + d] / den : 0.f;
    g_A[g * 384 + d] = g_A[g * 384 + 256 + d];   // q = h
    g_A[g * 384 + 128 + d] = r;
}

// ---------------- host ----------------
extern "C" void kernel_launch(void* const* d_in, const int* in_sizes, int n_in,
                              void* d_out, int out_size) {
    const float* x    = (const float*)d_in[0];
    const int*   ei   = (const int*)d_in[1];
    const int*   batch= (const int*)d_in[2];
    const float* W1l  = (const float*)d_in[3];
    const float* b1l  = (const float*)d_in[4];
    const float* W1r  = (const float*)d_in[5];
    const float* g1   = (const float*)d_in[6];
    const float* be1  = (const float*)d_in[7];
    const float* rm1  = (const float*)d_in[8];
    const float* rv1  = (const float*)d_in[9];
    const float* W2l  = (const float*)d_in[10];
    const float* b2l  = (const float*)d_in[11];
    const float* W2r  = (const float*)d_in[12];
    const float* g2   = (const float*)d_in[13];
    const float* be2  = (const float*)d_in[14];
    const float* rm2  = (const float*)d_in[15];
    const float* rv2  = (const float*)d_in[16];
    const float* Wih  = (const float*)d_in[17];
    const float* Whh  = (const float*)d_in[18];
    const float* bih  = (const float*)d_in[19];
    const float* bhh  = (const float*)d_in[20];
    const float* Wp   = (const float*)d_in[21];
    const float* bp   = (const float*)d_in[22];

    float *p_agg, *p_cnt, *p_h1, *p_h2, *p_A, *p_c, *p_gates, *p_Wl, *p_bl;
    float *p_inv, *p_s1, *p_t1, *p_s2, *p_t2;
    cudaGetSymbolAddress((void**)&p_agg, g_agg);
    cudaGetSymbolAddress((void**)&p_cnt, g_cnt);
    cudaGetSymbolAddress((void**)&p_inv, g_inv);
    cudaGetSymbolAddress((void**)&p_h1, g_h1);
    cudaGetSymbolAddress((void**)&p_h2, g_h2);
    cudaGetSymbolAddress((void**)&p_A, g_A);
    cudaGetSymbolAddress((void**)&p_c, g_c);
    cudaGetSymbolAddress((void**)&p_gates, g_gates);
    cudaGetSymbolAddress((void**)&p_Wl, g_Wl);
    cudaGetSymbolAddress((void**)&p_bl, g_bl);
    cudaGetSymbolAddress((void**)&p_s1, g_s1);
    cudaGetSymbolAddress((void**)&p_t1, g_t1);
    cudaGetSymbolAddress((void**)&p_s2, g_s2);
    cudaGetSymbolAddress((void**)&p_t2, g_t2);

    // prep
    k_zero<<<(NN * 128 + 255) / 256, 256>>>(p_agg, NN * 128);
    k_zero<<<(NN + 255) / 256, 256>>>(p_cnt, NN);
    k_zero<<<(BB * 384 + 255) / 256, 256>>>(p_A, BB * 384);
    k_zero<<<(BB * 128 + 255) / 256, 256>>>(p_c, BB * 128);
    k_bnprep<<<1, 256>>>(g1, be1, rm1, rv1, g2, be2, rm2, rv2);
    k_pack<<<(512 * 384 + 255) / 256, 256>>>(Wih, Whh, bih, bhh);

    // layer 1
    k_scatter<<<(EE * 32 + 255) / 256, 256>>>(x, ei, p_agg, p_cnt, 1);
    k_invcnt<<<(NN + 255) / 256, 256>>>();
    k_layer_gemm<<<NN / 64, 256>>>(p_agg, x, p_inv, W1l, W1r, b1l, p_s1, p_t1, p_h1);

    // layer 2
    k_zero<<<(NN * 128 + 255) / 256, 256>>>(p_agg, NN * 128);
    k_scatter<<<(EE * 32 + 255) / 256, 256>>>(p_h1, ei, p_agg, nullptr, 0);
    k_layer_gemm<<<NN / 64, 256>>>(p_agg, p_h1, p_inv, W2l, W2r, b2l, p_s2, p_t2, p_h2);

    // set2set (3 steps)
    for (int s = 0; s < 3; s++) {
        dim3 gg(BB / 64, 512 / 128);
        k_gemm<<<gg, 256>>>(p_A, 384, p_Wl, 384, p_bl, p_gates, 512, 384);
        k_lstm<<<BB, 128>>>();
        k_attn_e<<<(NN * 32 + 255) / 256, 256>>>(batch);
        k_attn_r<<<(NN * 32 + 255) / 256, 256>>>(batch);
        k_qstar<<<BB, 128>>>();
    }

    // final projection
    dim3 gf(BB / 64, 1);
    k_gemm<<<gf, 256>>>(p_A, 384, Wp, 256, bp, (float*)d_out, 128, 256);
}

// round 2
// speedup vs baseline: 1.6080x; 1.6080x over previous
#include <cuda_runtime.h>
#include <cuda_bf16.h>
#include <cstdint>

#define NN 40000
#define EE 640000
#define BB 256

// ---------------- scratch (device globals; no allocation) ----------------
__device__ float g_y[NN * 256];        // per-layer GEMM output [yl | yr]
__device__ float g_h1[NN * 128];
__device__ float g_h2[NN * 128];
__device__ float g_inv[NN];
__device__ int   g_dc[2 * NN];         // deg | cursor
__device__ int   g_start[NN + 1];
__device__ int   g_csr[EE];            // src ids sorted by dst
__device__ int   g_seg[BB + 1];
__device__ float g_A[BB * 384];        // cols 0:256 q_star, 256:384 h
__device__ float g_c[BB * 128];
__device__ float g_gates[BB * 512];
__device__ float g_Wl[512 * 384];      // packed [Wih | Whh]
__device__ float g_bl[512];            // bih + bhh
__device__ float g_s1[128], g_t1[128], g_s2[128], g_t2[128];

// ---------------- helpers ----------------
__device__ __forceinline__ float sigmoidf_(float x) { return 1.f / (1.f + expf(-x)); }

__device__ __forceinline__ float to_tf32(float x) {
    uint32_t u;
    asm("cvt.rna.tf32.f32 %0, %1;" : "=r"(u) : "f"(x));
    return __uint_as_float(u);
}

__device__ __forceinline__ void mma_tf32(float c[4], uint32_t a0, uint32_t a1,
                                         uint32_t a2, uint32_t a3,
                                         uint32_t b0, uint32_t b1) {
    asm volatile(
        "mma.sync.aligned.m16n8k8.row.col.f32.tf32.tf32.f32 "
        "{%0,%1,%2,%3}, {%4,%5,%6,%7}, {%8,%9}, {%0,%1,%2,%3};\n"
        : "+f"(c[0]), "+f"(c[1]), "+f"(c[2]), "+f"(c[3])
        : "r"(a0), "r"(a1), "r"(a2), "r"(a3), "r"(b0), "r"(b1));
}

// ---------------- tiny prep kernels ----------------
__global__ void k_zero(float* p, int n) {
    int i = blockIdx.x * blockDim.x + threadIdx.x;
    if (i < n) p[i] = 0.f;
}

__global__ void k_bnprep(const float* g1, const float* be1, const float* rm1, const float* rv1,
                         const float* b1l,
                         const float* g2, const float* be2, const float* rm2, const float* rv2,
                         const float* b2l) {
    int i = threadIdx.x;
    if (i < 128) {
        float s = g1[i] * rsqrtf(rv1[i] + 1e-5f);
        g_s1[i] = s; g_t1[i] = be1[i] + (b1l[i] - rm1[i]) * s;  // fold lin_l bias into t
    } else {
        int j = i - 128;
        float s = g2[j] * rsqrtf(rv2[j] + 1e-5f);
        g_s2[j] = s; g_t2[j] = be2[j] + (b2l[j] - rm2[j]) * s;
    }
}

__global__ void k_pack(const float* Wih, const float* Whh, const float* bih, const float* bhh) {
    int i = blockIdx.x * blockDim.x + threadIdx.x;
    if (i < 512 * 384) {
        int r = i / 384, k = i % 384;
        g_Wl[i] = (k < 256) ? Wih[r * 256 + k] : Whh[r * 128 + (k - 256)];
    }
    if (i < 512) g_bl[i] = bih[i] + bhh[i];
}

// ---------------- CSR build ----------------
__global__ void k_hist(const int* __restrict__ ei) {
    int e = blockIdx.x * blockDim.x + threadIdx.x;
    if (e < EE) atomicAdd(&g_dc[ei[EE + e]], 1);
}

__global__ void k_scan() {  // single block, 256 threads
    __shared__ int part[256];
    int tid = threadIdx.x;
    const int chunk = (NN + 255) / 256;
    int b0 = tid * chunk, b1 = min(b0 + chunk, NN);
    int s = 0;
    for (int i = b0; i < b1; i++) s += g_dc[i];
    part[tid] = s;
    __syncthreads();
    for (int off = 1; off < 256; off <<= 1) {
        int v = (tid >= off) ? part[tid - off] : 0;
        __syncthreads();
        part[tid] += v;
        __syncthreads();
    }
    int base = (tid == 0) ? 0 : part[tid - 1];
    for (int i = b0; i < b1; i++) {
        int d = g_dc[i];
        g_start[i] = base;
        g_inv[i] = 1.f / (float)max(d, 1);
        base += d;
    }
    if (tid == 255) g_start[NN] = base;
}

__global__ void k_fill(const int* __restrict__ ei) {
    int e = blockIdx.x * blockDim.x + threadIdx.x;
    if (e >= EE) return;
    int s = ei[e], d = ei[EE + e];
    int pos = g_start[d] + atomicAdd(&g_dc[NN + d], 1);
    g_csr[pos] = s;
}

__global__ void k_seg(const int* __restrict__ batch) {
    int i = blockIdx.x * blockDim.x + threadIdx.x;
    if (i >= NN) return;
    int b = batch[i];
    int prev = (i == 0) ? -1 : batch[i - 1];
    for (int q = prev + 1; q <= b; q++) g_seg[q] = i;
    if (i == NN - 1)
        for (int q = b + 1; q <= BB; q++) g_seg[q] = NN;
}

// ---------------- tf32 tensor-core GEMM: Y[:,half] = A @ W^T ----------------
// A [NN,128], W (Wl or Wr) [128,128], Y [NN,256]. Block tile 128x128, 8 warps (4m x 2n),
// warp tile 32x64, mma m16n8k8 tf32.
__global__ __launch_bounds__(256) void k_gemm_tf32(
    const float* __restrict__ A,
    const float* __restrict__ Wl, const float* __restrict__ Wr,
    float* __restrict__ Y) {
    __shared__ float As[32][133];   // [k][m]
    __shared__ float Bs[32][133];   // [k][n]
    const float* W = blockIdx.y ? Wr : Wl;
    int m0 = blockIdx.x * 128;
    int tid = threadIdx.x;
    int warp = tid >> 5, lane = tid & 31;
    int wm = warp >> 1, wn = warp & 1;
    int gid = lane >> 2, tig = lane & 3;

    float acc[2][8][4];
#pragma unroll
    for (int i = 0; i < 2; i++)
#pragma unroll
        for (int j = 0; j < 8; j++)
#pragma unroll
            for (int q = 0; q < 4; q++) acc[i][j][q] = 0.f;

    int lrow = tid >> 3;          // 0..31
    int lk4 = (tid & 7) * 4;      // 0..28

    for (int kc = 0; kc < 128; kc += 32) {
#pragma unroll
        for (int i = 0; i < 4; i++) {
            int r = m0 + lrow + 32 * i;
            int rc = min(r, NN - 1);
            float4 v = *(const float4*)(A + (size_t)rc * 128 + kc + lk4);
            As[lk4 + 0][lrow + 32 * i] = to_tf32(v.x);
            As[lk4 + 1][lrow + 32 * i] = to_tf32(v.y);
            As[lk4 + 2][lrow + 32 * i] = to_tf32(v.z);
            As[lk4 + 3][lrow + 32 * i] = to_tf32(v.w);
            float4 w = *(const float4*)(W + (size_t)(lrow + 32 * i) * 128 + kc + lk4);
            Bs[lk4 + 0][lrow + 32 * i] = to_tf32(w.x);
            Bs[lk4 + 1][lrow + 32 * i] = to_tf32(w.y);
            Bs[lk4 + 2][lrow + 32 * i] = to_tf32(w.z);
            Bs[lk4 + 3][lrow + 32 * i] = to_tf32(w.w);
        }
        __syncthreads();
#pragma unroll
        for (int ks = 0; ks < 32; ks += 8) {
            uint32_t a[2][4];
#pragma unroll
            for (int mt = 0; mt < 2; mt++) {
                int mb = wm * 32 + mt * 16;
                a[mt][0] = __float_as_uint(As[ks + tig][mb + gid]);
                a[mt][1] = __float_as_uint(As[ks + tig][mb + gid + 8]);
                a[mt][2] = __float_as_uint(As[ks + tig + 4][mb + gid]);
                a[mt][3] = __float_as_uint(As[ks + tig + 4][mb + gid + 8]);
            }
#pragma unroll
            for (int nt = 0; nt < 8; nt++) {
                int nb = wn * 64 + nt * 8;
                uint32_t b0 = __float_as_uint(Bs[ks + tig][nb + gid]);
                uint32_t b1 = __float_as_uint(Bs[ks + tig + 4][nb + gid]);
                mma_tf32(acc[0][nt], a[0][0], a[0][1], a[0][2], a[0][3], b0, b1);
                mma_tf32(acc[1][nt], a[1][0], a[1][1], a[1][2], a[1][3], b0, b1);
            }
        }
        __syncthreads();
    }

    int ncol0 = blockIdx.y * 128 + wn * 64;
#pragma unroll
    for (int mt = 0; mt < 2; mt++) {
        int row0 = m0 + wm * 32 + mt * 16 + gid;
        int row1 = row0 + 8;
#pragma unroll
        for (int nt = 0; nt < 8; nt++) {
            int c = ncol0 + nt * 8 + tig * 2;
            if (row0 < NN) {
                float2 v = make_float2(acc[mt][nt][0], acc[mt][nt][1]);
                *(float2*)(Y + (size_t)row0 * 256 + c) = v;
            }
            if (row1 < NN) {
                float2 v = make_float2(acc[mt][nt][2], acc[mt][nt][3]);
                *(float2*)(Y + (size_t)row1 * 256 + c) = v;
            }
        }
    }
}

// ---------------- CSR aggregation + epilogue ----------------
// out[i] = relu(((sum_j yl[j]) * inv[i] + yr[i]) * s + t), warp per node
__global__ void k_agg(const float* __restrict__ Y,
                      const float* __restrict__ s, const float* __restrict__ t,
                      float* __restrict__ out) {
    int gt = blockIdx.x * blockDim.x + threadIdx.x;
    int w = gt >> 5;
    if (w >= NN) return;
    int lane = gt & 31;
    int e0 = g_start[w], e1 = g_start[w + 1];
    float4 acc = make_float4(0.f, 0.f, 0.f, 0.f);
    const float4* Y4 = (const float4*)Y;
    for (int e = e0; e < e1; e++) {
        int sn = __ldg(g_csr + e);
        float4 v = Y4[(size_t)sn * 64 + lane];
        acc.x += v.x; acc.y += v.y; acc.z += v.z; acc.w += v.w;
    }
    float iv = g_inv[w];
    float4 yr = Y4[(size_t)w * 64 + 32 + lane];
    float4 sv = ((const float4*)s)[lane];
    float4 tv = ((const float4*)t)[lane];
    float4 o;
    o.x = fmaxf(fmaf(fmaf(acc.x, iv, yr.x), sv.x, tv.x), 0.f);
    o.y = fmaxf(fmaf(fmaf(acc.y, iv, yr.y), sv.y, tv.y), 0.f);
    o.z = fmaxf(fmaf(fmaf(acc.z, iv, yr.z), sv.z, tv.z), 0.f);
    o.w = fmaxf(fmaf(fmaf(acc.w, iv, yr.w), sv.w, tv.w), 0.f);
    ((float4*)out)[(size_t)w * 32 + lane] = o;
}

// ---------------- generic SIMT GEMM: out = A @ W^T + bias ----------------
__global__ __launch_bounds__(256) void k_gemm(const float* __restrict__ A, int lda,
                                              const float* __restrict__ W, int ldw,
                                              const float* __restrict__ bias,
                                              float* __restrict__ out, int ldo, int K) {
    __shared__ float As[16][65];
    __shared__ float Ws[16][132];
    int tid = threadIdx.x;
    int m0 = blockIdx.x * 64, n0 = blockIdx.y * 128;
    int lr = tid >> 2;
    int lk = (tid & 3) * 4;
    int ty = tid >> 4, tx = tid & 15;
    int ty4 = ty * 4, tx8 = tx * 8;

    float acc[4][8];
#pragma unroll
    for (int i = 0; i < 4; i++)
#pragma unroll
        for (int j = 0; j < 8; j++) acc[i][j] = 0.f;

    for (int k0 = 0; k0 < K; k0 += 16) {
        float4 av = *(const float4*)(A + (size_t)(m0 + lr) * lda + k0 + lk);
        float4 w0 = *(const float4*)(W + (size_t)(n0 + lr) * ldw + k0 + lk);
        float4 w1 = *(const float4*)(W + (size_t)(n0 + lr + 64) * ldw + k0 + lk);
        As[lk + 0][lr] = av.x; As[lk + 1][lr] = av.y; As[lk + 2][lr] = av.z; As[lk + 3][lr] = av.w;
        Ws[lk + 0][lr] = w0.x; Ws[lk + 1][lr] = w0.y; Ws[lk + 2][lr] = w0.z; Ws[lk + 3][lr] = w0.w;
        Ws[lk + 0][64 + lr] = w1.x; Ws[lk + 1][64 + lr] = w1.y; Ws[lk + 2][64 + lr] = w1.z; Ws[lk + 3][64 + lr] = w1.w;
        __syncthreads();
#pragma unroll
        for (int k = 0; k < 16; k++) {
            float a0 = As[k][ty4], a1 = As[k][ty4 + 1], a2 = As[k][ty4 + 2], a3 = As[k][ty4 + 3];
            float4 wa = *(float4*)&Ws[k][tx8];
            float4 wb = *(float4*)&Ws[k][tx8 + 4];
            acc[0][0] += a0 * wa.x; acc[0][1] += a0 * wa.y; acc[0][2] += a0 * wa.z; acc[0][3] += a0 * wa.w;
            acc[0][4] += a0 * wb.x; acc[0][5] += a0 * wb.y; acc[0][6] += a0 * wb.z; acc[0][7] += a0 * wb.w;
            acc[1][0] += a1 * wa.x; acc[1][1] += a1 * wa.y; acc[1][2] += a1 * wa.z; acc[1][3] += a1 * wa.w;
            acc[1][4] += a1 * wb.x; acc[1][5] += a1 * wb.y; acc[1][6] += a1 * wb.z; acc[1][7] += a1 * wb.w;
            acc[2][0] += a2 * wa.x; acc[2][1] += a2 * wa.y; acc[2][2] += a2 * wa.z; acc[2][3] += a2 * wa.w;
            acc[2][4] += a2 * wb.x; acc[2][5] += a2 * wb.y; acc[2][6] += a2 * wb.z; acc[2][7] += a2 * wb.w;
            acc[3][0] += a3 * wa.x; acc[3][1] += a3 * wa.y; acc[3][2] += a3 * wa.z; acc[3][3] += a3 * wa.w;
            acc[3][4] += a3 * wb.x; acc[3][5] += a3 * wb.y; acc[3][6] += a3 * wb.z; acc[3][7] += a3 * wb.w;
        }
        __syncthreads();
    }
#pragma unroll
    for (int i = 0; i < 4; i++) {
        int m = m0 + ty4 + i;
#pragma unroll
        for (int j = 0; j < 8; j++) {
            int n = n0 + tx8 + j;
            out[(size_t)m * ldo + n] = acc[i][j] + bias[n];
        }
    }
}

// ---------------- fused set2set step: LSTM cell + segment softmax attention ----------------
// one block (128 threads) per graph; batch is sorted so segments are contiguous
__global__ __launch_bounds__(128) void k_step() {
    int g = blockIdx.x;
    int tid = threadIdx.x;
    int wid = tid >> 5, lane = tid & 31;
    __shared__ float sh_q[128];
    __shared__ float sh_r[4][128];
    __shared__ float sh_s[8];

    // LSTM cell
    {
        const float* gt = g_gates + g * 512;
        float ig = gt[tid], fg = gt[128 + tid], gg = gt[256 + tid], og = gt[384 + tid];
        float c0 = g_c[g * 128 + tid];
        float cn = sigmoidf_(fg) * c0 + sigmoidf_(ig) * tanhf(gg);
        float hn = sigmoidf_(og) * tanhf(cn);
        g_c[g * 128 + tid] = cn;
        sh_q[tid] = hn;
    }
    __syncthreads();

    int s0 = g_seg[g], s1 = g_seg[g + 1];
    const float4* H4 = (const float4*)g_h2;
    float4 qv = ((const float4*)sh_q)[lane];

    // pass 1: segment max of e = <h2[n], q>
    float wmax = -3.402823466e38f;
    for (int n = s0 + wid; n < s1; n += 4) {
        float4 hv = H4[(size_t)n * 32 + lane];
        float p = hv.x * qv.x + hv.y * qv.y + hv.z * qv.z + hv.w * qv.w;
#pragma unroll
        for (int o = 16; o > 0; o >>= 1) p += __shfl_xor_sync(0xffffffffu, p, o);
        wmax = fmaxf(wmax, p);
    }
    if (lane == 0) sh_s[wid] = wmax;
    __syncthreads();
    float emax = fmaxf(fmaxf(sh_s[0], sh_s[1]), fmaxf(sh_s[2], sh_s[3]));

    // pass 2: exp-sum + weighted feature sum
    float asum = 0.f;
    float4 racc = make_float4(0.f, 0.f, 0.f, 0.f);
    for (int n = s0 + wid; n < s1; n += 4) {
        float4 hv = H4[(size_t)n * 32 + lane];
        float p = hv.x * qv.x + hv.y * qv.y + hv.z * qv.z + hv.w * qv.w;
#pragma unroll
        for (int o = 16; o > 0; o >>= 1) p += __shfl_xor_sync(0xffffffffu, p, o);
        float a = expf(p - emax);
        asum += a;
        racc.x += a * hv.x; racc.y += a * hv.y; racc.z += a * hv.z; racc.w += a * hv.w;
    }
    ((float4*)sh_r[wid])[lane] = racc;
    if (lane == 0) sh_s[4 + wid] = asum;
    __syncthreads();

    float den = sh_s[4] + sh_s[5] + sh_s[6] + sh_s[7];
    float rsum = sh_r[0][tid] + sh_r[1][tid] + sh_r[2][tid] + sh_r[3][tid];
    float r = (den > 0.f) ? rsum / den : 0.f;
    g_A[g * 384 + tid] = sh_q[tid];            // q = h
    g_A[g * 384 + 128 + tid] = r;              // r
    g_A[g * 384 + 256 + tid] = sh_q[tid];      // h (for next LSTM input via packed W)
}

// ---------------- host ----------------
extern "C" void kernel_launch(void* const* d_in, const int* in_sizes, int n_in,
                              void* d_out, int out_size) {
    const float* x    = (const float*)d_in[0];
    const int*   ei   = (const int*)d_in[1];
    const int*   batch= (const int*)d_in[2];
    const float* W1l  = (const float*)d_in[3];
    const float* b1l  = (const float*)d_in[4];
    const float* W1r  = (const float*)d_in[5];
    const float* g1   = (const float*)d_in[6];
    const float* be1  = (const float*)d_in[7];
    const float* rm1  = (const float*)d_in[8];
    const float* rv1  = (const float*)d_in[9];
    const float* W2l  = (const float*)d_in[10];
    const float* b2l  = (const float*)d_in[11];
    const float* W2r  = (const float*)d_in[12];
    const float* g2   = (const float*)d_in[13];
    const float* be2  = (const float*)d_in[14];
    const float* rm2  = (const float*)d_in[15];
    const float* rv2  = (const float*)d_in[16];
    const float* Wih  = (const float*)d_in[17];
    const float* Whh  = (const float*)d_in[18];
    const float* bih  = (const float*)d_in[19];
    const float* bhh  = (const float*)d_in[20];
    const float* Wp   = (const float*)d_in[21];
    const float* bp   = (const float*)d_in[22];

    float *p_y, *p_h1, *p_h2, *p_A, *p_c, *p_gates, *p_Wl, *p_bl;
    float *p_s1, *p_t1, *p_s2, *p_t2;
    int *p_dc;
    cudaGetSymbolAddress((void**)&p_y, g_y);
    cudaGetSymbolAddress((void**)&p_h1, g_h1);
    cudaGetSymbolAddress((void**)&p_h2, g_h2);
    cudaGetSymbolAddress((void**)&p_A, g_A);
    cudaGetSymbolAddress((void**)&p_c, g_c);
    cudaGetSymbolAddress((void**)&p_gates, g_gates);
    cudaGetSymbolAddress((void**)&p_Wl, g_Wl);
    cudaGetSymbolAddress((void**)&p_bl, g_bl);
    cudaGetSymbolAddress((void**)&p_s1, g_s1);
    cudaGetSymbolAddress((void**)&p_t1, g_t1);
    cudaGetSymbolAddress((void**)&p_s2, g_s2);
    cudaGetSymbolAddress((void**)&p_t2, g_t2);
    cudaGetSymbolAddress((void**)&p_dc, g_dc);

    // prep
    k_zero<<<(BB * 384 + 255) / 256, 256>>>(p_A, BB * 384);
    k_zero<<<(BB * 128 + 255) / 256, 256>>>(p_c, BB * 128);
    k_zero<<<(2 * NN + 255) / 256, 256>>>((float*)p_dc, 2 * NN);
    k_bnprep<<<1, 256>>>(g1, be1, rm1, rv1, b1l, g2, be2, rm2, rv2, b2l);
    k_pack<<<(512 * 384 + 255) / 256, 256>>>(Wih, Whh, bih, bhh);

    // CSR build + segment boundaries
    k_hist<<<(EE + 255) / 256, 256>>>(ei);
    k_scan<<<1, 256>>>();
    k_fill<<<(EE + 255) / 256, 256>>>(ei);
    k_seg<<<(NN + 255) / 256, 256>>>(batch);

    dim3 gL((NN + 127) / 128, 2);
    // layer 1: Y = [x@W1l^T | x@W1r^T], then h1 = relu(BN(mean_agg(yl) + yr))
    k_gemm_tf32<<<gL, 256>>>(x, W1l, W1r, p_y);
    k_agg<<<(NN * 32 + 255) / 256, 256>>>(p_y, p_s1, p_t1, p_h1);
    // layer 2
    k_gemm_tf32<<<gL, 256>>>(p_h1, W2l, W2r, p_y);
    k_agg<<<(NN * 32 + 255) / 256, 256>>>(p_y, p_s2, p_t2, p_h2);

    // set2set (3 steps): gates GEMM + fused step
    for (int s = 0; s < 3; s++) {
        dim3 gg(BB / 64, 512 / 128);
        k_gemm<<<gg, 256>>>(p_A, 384, p_Wl, 384, p_bl, p_gates, 512, 384);
        k_step<<<BB, 128>>>();
    }

    // final projection: out = q_star @ Wp^T + bp
    dim3 gf(BB / 64, 1);
    k_gemm<<<gf, 256>>>(p_A, 384, Wp, 256, bp, (float*)d_out, 128, 256);
}

// round 3
// speedup vs baseline: 2.4196x; 1.5048x over previous
#include <cuda_runtime.h>
#include <cuda_bf16.h>
#include <cstdint>

#define NN 40000
#define EE 640000
#define BB 256

// ---------------- scratch (device globals; no allocation) ----------------
__device__ float g_y[NN * 256];        // per-layer GEMM output [yl | yr]
__device__ float g_h1[NN * 128];
__device__ float g_h2[NN * 128];
__device__ float g_inv[NN];
__device__ int   g_dc[2 * NN];         // deg | cursor
__device__ int   g_start[NN + 1];
__device__ int   g_csr[EE];            // src ids sorted by dst
__device__ int   g_seg[BB + 1];
__device__ float g_A[BB * 256];        // [h | r] per graph
__device__ float g_c[BB * 128];
__device__ float g_Wc[512 * 256];      // [Wih[:,:128]+Whh | Wih[:,128:]]
__device__ float g_bl[512];            // bih + bhh
__device__ float g_s1[128], g_t1[128], g_s2[128], g_t2[128];

// ---------------- helpers ----------------
__device__ __forceinline__ float sigmoidf_(float x) { return 1.f / (1.f + expf(-x)); }

__device__ __forceinline__ float to_tf32(float x) {
    uint32_t u;
    asm("cvt.rna.tf32.f32 %0, %1;" : "=r"(u) : "f"(x));
    return __uint_as_float(u);
}

__device__ __forceinline__ void mma_tf32(float c[4], uint32_t a0, uint32_t a1,
                                         uint32_t a2, uint32_t a3,
                                         uint32_t b0, uint32_t b1) {
    asm volatile(
        "mma.sync.aligned.m16n8k8.row.col.f32.tf32.tf32.f32 "
        "{%0,%1,%2,%3}, {%4,%5,%6,%7}, {%8,%9}, {%0,%1,%2,%3};\n"
        : "+f"(c[0]), "+f"(c[1]), "+f"(c[2]), "+f"(c[3])
        : "r"(a0), "r"(a1), "r"(a2), "r"(a3), "r"(b0), "r"(b1));
}

// ---------------- fused prep: pack Wc/bl, fold BN, zero counters, seg bounds ----------------
__global__ void k_prep(const float* __restrict__ Wih, const float* __restrict__ Whh,
                       const float* __restrict__ bih, const float* __restrict__ bhh,
                       const float* __restrict__ g1, const float* __restrict__ be1,
                       const float* __restrict__ rm1, const float* __restrict__ rv1,
                       const float* __restrict__ b1l,
                       const float* __restrict__ g2, const float* __restrict__ be2,
                       const float* __restrict__ rm2, const float* __restrict__ rv2,
                       const float* __restrict__ b2l,
                       const int* __restrict__ batch) {
    int i = blockIdx.x * blockDim.x + threadIdx.x;
    if (i < 512 * 256) {
        int r = i >> 8, k = i & 255;
        float w = Wih[r * 256 + k];
        if (k < 128) w += Whh[r * 128 + k];
        g_Wc[i] = w;
    }
    if (i < 512) g_bl[i] = bih[i] + bhh[i];
    if (i < 128) {
        float s = g1[i] * rsqrtf(rv1[i] + 1e-5f);
        g_s1[i] = s; g_t1[i] = be1[i] + (b1l[i] - rm1[i]) * s;
    } else if (i < 256) {
        int j = i - 128;
        float s = g2[j] * rsqrtf(rv2[j] + 1e-5f);
        g_s2[j] = s; g_t2[j] = be2[j] + (b2l[j] - rm2[j]) * s;
    }
    if (i < NN) {
        g_dc[i] = 0; g_dc[NN + i] = 0;
        int b = batch[i];
        int prev = (i == 0) ? -1 : batch[i - 1];
        for (int q = prev + 1; q <= b; q++) g_seg[q] = i;
        if (i == NN - 1)
            for (int q = b + 1; q <= BB; q++) g_seg[q] = NN;
    }
}

// ---------------- CSR build ----------------
__global__ void k_hist(const int* __restrict__ ei) {
    int e = blockIdx.x * blockDim.x + threadIdx.x;
    if (e < EE) atomicAdd(&g_dc[ei[EE + e]], 1);
}

__global__ void k_scan() {  // single block, 256 threads
    __shared__ int part[256];
    int tid = threadIdx.x;
    const int chunk = (NN + 255) / 256;
    int b0 = tid * chunk, b1 = min(b0 + chunk, NN);
    int s = 0;
    for (int i = b0; i < b1; i++) s += g_dc[i];
    part[tid] = s;
    __syncthreads();
    for (int off = 1; off < 256; off <<= 1) {
        int v = (tid >= off) ? part[tid - off] : 0;
        __syncthreads();
        part[tid] += v;
        __syncthreads();
    }
    int base = (tid == 0) ? 0 : part[tid - 1];
    for (int i = b0; i < b1; i++) {
        int d = g_dc[i];
        g_start[i] = base;
        g_inv[i] = 1.f / (float)max(d, 1);
        base += d;
    }
    if (tid == 255) g_start[NN] = base;
}

__global__ void k_fill(const int* __restrict__ ei) {
    int e = blockIdx.x * blockDim.x + threadIdx.x;
    if (e >= EE) return;
    int s = ei[e], d = ei[EE + e];
    int pos = g_start[d] + atomicAdd(&g_dc[NN + d], 1);
    g_csr[pos] = s;
}

// ---------------- tf32 tensor-core GEMM: Y[:,half] = A @ W^T ----------------
__global__ __launch_bounds__(256) void k_gemm_tf32(
    const float* __restrict__ A,
    const float* __restrict__ Wl, const float* __restrict__ Wr,
    float* __restrict__ Y) {
    __shared__ float As[32][133];   // [k][m]
    __shared__ float Bs[32][133];   // [k][n]
    const float* W = blockIdx.y ? Wr : Wl;
    int m0 = blockIdx.x * 128;
    int tid = threadIdx.x;
    int warp = tid >> 5, lane = tid & 31;
    int wm = warp >> 1, wn = warp & 1;
    int gid = lane >> 2, tig = lane & 3;

    float acc[2][8][4];
#pragma unroll
    for (int i = 0; i < 2; i++)
#pragma unroll
        for (int j = 0; j < 8; j++)
#pragma unroll
            for (int q = 0; q < 4; q++) acc[i][j][q] = 0.f;

    int lrow = tid >> 3;          // 0..31
    int lk4 = (tid & 7) * 4;      // 0..28

    for (int kc = 0; kc < 128; kc += 32) {
#pragma unroll
        for (int i = 0; i < 4; i++) {
            int r = m0 + lrow + 32 * i;
            int rc = min(r, NN - 1);
            float4 v = *(const float4*)(A + (size_t)rc * 128 + kc + lk4);
            As[lk4 + 0][lrow + 32 * i] = to_tf32(v.x);
            As[lk4 + 1][lrow + 32 * i] = to_tf32(v.y);
            As[lk4 + 2][lrow + 32 * i] = to_tf32(v.z);
            As[lk4 + 3][lrow + 32 * i] = to_tf32(v.w);
            float4 w = *(const float4*)(W + (size_t)(lrow + 32 * i) * 128 + kc + lk4);
            Bs[lk4 + 0][lrow + 32 * i] = to_tf32(w.x);
            Bs[lk4 + 1][lrow + 32 * i] = to_tf32(w.y);
            Bs[lk4 + 2][lrow + 32 * i] = to_tf32(w.z);
            Bs[lk4 + 3][lrow + 32 * i] = to_tf32(w.w);
        }
        __syncthreads();
#pragma unroll
        for (int ks = 0; ks < 32; ks += 8) {
            uint32_t a[2][4];
#pragma unroll
            for (int mt = 0; mt < 2; mt++) {
                int mb = wm * 32 + mt * 16;
                a[mt][0] = __float_as_uint(As[ks + tig][mb + gid]);
                a[mt][1] = __float_as_uint(As[ks + tig][mb + gid + 8]);
                a[mt][2] = __float_as_uint(As[ks + tig + 4][mb + gid]);
                a[mt][3] = __float_as_uint(As[ks + tig + 4][mb + gid + 8]);
            }
#pragma unroll
            for (int nt = 0; nt < 8; nt++) {
                int nb = wn * 64 + nt * 8;
                uint32_t b0 = __float_as_uint(Bs[ks + tig][nb + gid]);
                uint32_t b1 = __float_as_uint(Bs[ks + tig + 4][nb + gid]);
                mma_tf32(acc[0][nt], a[0][0], a[0][1], a[0][2], a[0][3], b0, b1);
                mma_tf32(acc[1][nt], a[1][0], a[1][1], a[1][2], a[1][3], b0, b1);
            }
        }
        __syncthreads();
    }

    int ncol0 = blockIdx.y * 128 + wn * 64;
#pragma unroll
    for (int mt = 0; mt < 2; mt++) {
        int row0 = m0 + wm * 32 + mt * 16 + gid;
        int row1 = row0 + 8;
#pragma unroll
        for (int nt = 0; nt < 8; nt++) {
            int c = ncol0 + nt * 8 + tig * 2;
            if (row0 < NN) {
                float2 v = make_float2(acc[mt][nt][0], acc[mt][nt][1]);
                *(float2*)(Y + (size_t)row0 * 256 + c) = v;
            }
            if (row1 < NN) {
                float2 v = make_float2(acc[mt][nt][2], acc[mt][nt][3]);
                *(float2*)(Y + (size_t)row1 * 256 + c) = v;
            }
        }
    }
}

// ---------------- CSR aggregation + epilogue (unrolled x2) ----------------
__global__ void k_agg(const float* __restrict__ Y,
                      const float* __restrict__ s, const float* __restrict__ t,
                      float* __restrict__ out) {
    int gt = blockIdx.x * blockDim.x + threadIdx.x;
    int w = gt >> 5;
    if (w >= NN) return;
    int lane = gt & 31;
    int e0 = g_start[w], e1 = g_start[w + 1];
    float4 acc0 = make_float4(0.f, 0.f, 0.f, 0.f);
    float4 acc1 = make_float4(0.f, 0.f, 0.f, 0.f);
    const float4* Y4 = (const float4*)Y;
    int e = e0;
    for (; e + 2 <= e1; e += 2) {
        int sa = __ldg(g_csr + e);
        int sb = __ldg(g_csr + e + 1);
        float4 va = Y4[(size_t)sa * 64 + lane];
        float4 vb = Y4[(size_t)sb * 64 + lane];
        acc0.x += va.x; acc0.y += va.y; acc0.z += va.z; acc0.w += va.w;
        acc1.x += vb.x; acc1.y += vb.y; acc1.z += vb.z; acc1.w += vb.w;
    }
    if (e < e1) {
        int sa = __ldg(g_csr + e);
        float4 va = Y4[(size_t)sa * 64 + lane];
        acc0.x += va.x; acc0.y += va.y; acc0.z += va.z; acc0.w += va.w;
    }
    acc0.x += acc1.x; acc0.y += acc1.y; acc0.z += acc1.z; acc0.w += acc1.w;
    float iv = g_inv[w];
    float4 yr = Y4[(size_t)w * 64 + 32 + lane];
    float4 sv = ((const float4*)s)[lane];
    float4 tv = ((const float4*)t)[lane];
    float4 o;
    o.x = fmaxf(fmaf(fmaf(acc0.x, iv, yr.x), sv.x, tv.x), 0.f);
    o.y = fmaxf(fmaf(fmaf(acc0.y, iv, yr.y), sv.y, tv.y), 0.f);
    o.z = fmaxf(fmaf(fmaf(acc0.z, iv, yr.z), sv.z, tv.z), 0.f);
    o.w = fmaxf(fmaf(fmaf(acc0.w, iv, yr.w), sv.w, tv.w), 0.f);
    ((float4*)out)[(size_t)w * 32 + lane] = o;
}

// ---------------- fully fused set2set step ----------------
// one block (256 threads) per graph: gates GEMM (K=256) + LSTM + segment softmax attention
__global__ __launch_bounds__(256) void k_step(int first) {
    int g = blockIdx.x;
    int tid = threadIdx.x;
    int warp = tid >> 5, lane = tid & 31;
    __shared__ float sh_gates[512];
    __shared__ float sh_v[256];
    __shared__ float sh_q[128];
    __shared__ float sh_r[8][128];
    __shared__ float sh_s[16];

    if (!first) {
        sh_v[tid] = g_A[g * 256 + tid];
        __syncthreads();
        const float4* V4 = (const float4*)sh_v;
        float4 v0 = V4[lane];
        float4 v1 = V4[32 + lane];
        // 8 warps x 64 gate rows, warp-cooperative dot over K=256
#pragma unroll 4
        for (int j = 0; j < 64; j++) {
            int r = warp * 64 + j;
            const float4* Wr4 = (const float4*)(g_Wc + (size_t)r * 256);
            float4 w0 = Wr4[lane];
            float4 w1 = Wr4[32 + lane];
            float p = w0.x * v0.x + w0.y * v0.y + w0.z * v0.z + w0.w * v0.w
                    + w1.x * v1.x + w1.y * v1.y + w1.z * v1.z + w1.w * v1.w;
#pragma unroll
            for (int o = 16; o > 0; o >>= 1) p += __shfl_xor_sync(0xffffffffu, p, o);
            if (lane == 0) sh_gates[r] = p + g_bl[r];
        }
    } else {
        sh_gates[tid] = g_bl[tid];
        sh_gates[256 + tid] = g_bl[256 + tid];
    }
    __syncthreads();

    // LSTM cell
    if (tid < 128) {
        float ig = sh_gates[tid], fg = sh_gates[128 + tid];
        float gg = sh_gates[256 + tid], og = sh_gates[384 + tid];
        float c0 = first ? 0.f : g_c[g * 128 + tid];
        float cn = sigmoidf_(fg) * c0 + sigmoidf_(ig) * tanhf(gg);
        float hn = sigmoidf_(og) * tanhf(cn);
        g_c[g * 128 + tid] = cn;
        sh_q[tid] = hn;
    }
    __syncthreads();

    int s0 = g_seg[g], s1 = g_seg[g + 1];
    const float4* H4 = (const float4*)g_h2;
    float4 qv = ((const float4*)sh_q)[lane];

    // pass 1: segment max of e = <h2[n], q>
    float wmax = -3.402823466e38f;
    for (int n = s0 + warp; n < s1; n += 8) {
        float4 hv = H4[(size_t)n * 32 + lane];
        float p = hv.x * qv.x + hv.y * qv.y + hv.z * qv.z + hv.w * qv.w;
#pragma unroll
        for (int o = 16; o > 0; o >>= 1) p += __shfl_xor_sync(0xffffffffu, p, o);
        wmax = fmaxf(wmax, p);
    }
    if (lane == 0) sh_s[warp] = wmax;
    __syncthreads();
    float emax = sh_s[0];
#pragma unroll
    for (int j = 1; j < 8; j++) emax = fmaxf(emax, sh_s[j]);

    // pass 2: exp-sum + weighted feature sum
    float asum = 0.f;
    float4 racc = make_float4(0.f, 0.f, 0.f, 0.f);
    for (int n = s0 + warp; n < s1; n += 8) {
        float4 hv = H4[(size_t)n * 32 + lane];
        float p = hv.x * qv.x + hv.y * qv.y + hv.z * qv.z + hv.w * qv.w;
#pragma unroll
        for (int o = 16; o > 0; o >>= 1) p += __shfl_xor_sync(0xffffffffu, p, o);
        float a = expf(p - emax);
        asum += a;
        racc.x += a * hv.x; racc.y += a * hv.y; racc.z += a * hv.z; racc.w += a * hv.w;
    }
    ((float4*)sh_r[warp])[lane] = racc;
    if (lane == 0) sh_s[8 + warp] = asum;
    __syncthreads();

    if (tid < 128) {
        float den = 0.f;
#pragma unroll
        for (int j = 0; j < 8; j++) den += sh_s[8 + j];
        float rsum = 0.f;
#pragma unroll
        for (int j = 0; j < 8; j++) rsum += sh_r[j][tid];
        float r = (den > 0.f) ? rsum / den : 0.f;
        g_A[g * 256 + tid] = sh_q[tid];        // q = h
        g_A[g * 256 + 128 + tid] = r;          // r
    }
}

// ---------------- generic SIMT GEMM (final projection): out = A @ W^T + bias ----------------
__global__ __launch_bounds__(256) void k_gemm(const float* __restrict__ A, int lda,
                                              const float* __restrict__ W, int ldw,
                                              const float* __restrict__ bias,
                                              float* __restrict__ out, int ldo, int K) {
    __shared__ float As[16][65];
    __shared__ float Ws[16][132];
    int tid = threadIdx.x;
    int m0 = blockIdx.x * 64, n0 = blockIdx.y * 128;
    int lr = tid >> 2;
    int lk = (tid & 3) * 4;
    int ty = tid >> 4, tx = tid & 15;
    int ty4 = ty * 4, tx8 = tx * 8;

    float acc[4][8];
#pragma unroll
    for (int i = 0; i < 4; i++)
#pragma unroll
        for (int j = 0; j < 8; j++) acc[i][j] = 0.f;

    for (int k0 = 0; k0 < K; k0 += 16) {
        float4 av = *(const float4*)(A + (size_t)(m0 + lr) * lda + k0 + lk);
        float4 w0 = *(const float4*)(W + (size_t)(n0 + lr) * ldw + k0 + lk);
        float4 w1 = *(const float4*)(W + (size_t)(n0 + lr + 64) * ldw + k0 + lk);
        As[lk + 0][lr] = av.x; As[lk + 1][lr] = av.y; As[lk + 2][lr] = av.z; As[lk + 3][lr] = av.w;
        Ws[lk + 0][lr] = w0.x; Ws[lk + 1][lr] = w0.y; Ws[lk + 2][lr] = w0.z; Ws[lk + 3][lr] = w0.w;
        Ws[lk + 0][64 + lr] = w1.x; Ws[lk + 1][64 + lr] = w1.y; Ws[lk + 2][64 + lr] = w1.z; Ws[lk + 3][64 + lr] = w1.w;
        __syncthreads();
#pragma unroll
        for (int k = 0; k < 16; k++) {
            float a0 = As[k][ty4], a1 = As[k][ty4 + 1], a2 = As[k][ty4 + 2], a3 = As[k][ty4 + 3];
            float4 wa = *(float4*)&Ws[k][tx8];
            float4 wb = *(float4*)&Ws[k][tx8 + 4];
            acc[0][0] += a0 * wa.x; acc[0][1] += a0 * wa.y; acc[0][2] += a0 * wa.z; acc[0][3] += a0 * wa.w;
            acc[0][4] += a0 * wb.x; acc[0][5] += a0 * wb.y; acc[0][6] += a0 * wb.z; acc[0][7] += a0 * wb.w;
            acc[1][0] += a1 * wa.x; acc[1][1] += a1 * wa.y; acc[1][2] += a1 * wa.z; acc[1][3] += a1 * wa.w;
            acc[1][4] += a1 * wb.x; acc[1][5] += a1 * wb.y; acc[1][6] += a1 * wb.z; acc[1][7] += a1 * wb.w;
            acc[2][0] += a2 * wa.x; acc[2][1] += a2 * wa.y; acc[2][2] += a2 * wa.z; acc[2][3] += a2 * wa.w;
            acc[2][4] += a2 * wb.x; acc[2][5] += a2 * wb.y; acc[2][6] += a2 * wb.z; acc[2][7] += a2 * wb.w;
            acc[3][0] += a3 * wa.x; acc[3][1] += a3 * wa.y; acc[3][2] += a3 * wa.z; acc[3][3] += a3 * wa.w;
            acc[3][4] += a3 * wb.x; acc[3][5] += a3 * wb.y; acc[3][6] += a3 * wb.z; acc[3][7] += a3 * wb.w;
        }
        __syncthreads();
    }
#pragma unroll
    for (int i = 0; i < 4; i++) {
        int m = m0 + ty4 + i;
#pragma unroll
        for (int j = 0; j < 8; j++) {
            int n = n0 + tx8 + j;
            out[(size_t)m * ldo + n] = acc[i][j] + bias[n];
        }
    }
}

// ---------------- host ----------------
extern "C" void kernel_launch(void* const* d_in, const int* in_sizes, int n_in,
                              void* d_out, int out_size) {
    const float* x    = (const float*)d_in[0];
    const int*   ei   = (const int*)d_in[1];
    const int*   batch= (const int*)d_in[2];
    const float* W1l  = (const float*)d_in[3];
    const float* b1l  = (const float*)d_in[4];
    const float* W1r  = (const float*)d_in[5];
    const float* g1   = (const float*)d_in[6];
    const float* be1  = (const float*)d_in[7];
    const float* rm1  = (const float*)d_in[8];
    const float* rv1  = (const float*)d_in[9];
    const float* W2l  = (const float*)d_in[10];
    const float* b2l  = (const float*)d_in[11];
    const float* W2r  = (const float*)d_in[12];
    const float* g2   = (const float*)d_in[13];
    const float* be2  = (const float*)d_in[14];
    const float* rm2  = (const float*)d_in[15];
    const float* rv2  = (const float*)d_in[16];
    const float* Wih  = (const float*)d_in[17];
    const float* Whh  = (const float*)d_in[18];
    const float* bih  = (const float*)d_in[19];
    const float* bhh  = (const float*)d_in[20];
    const float* Wp   = (const float*)d_in[21];
    const float* bp   = (const float*)d_in[22];

    float *p_y, *p_h1, *p_h2, *p_A;
    float *p_s1, *p_t1, *p_s2, *p_t2;
    cudaGetSymbolAddress((void**)&p_y, g_y);
    cudaGetSymbolAddress((void**)&p_h1, g_h1);
    cudaGetSymbolAddress((void**)&p_h2, g_h2);
    cudaGetSymbolAddress((void**)&p_A, g_A);
    cudaGetSymbolAddress((void**)&p_s1, g_s1);
    cudaGetSymbolAddress((void**)&p_t1, g_t1);
    cudaGetSymbolAddress((void**)&p_s2, g_s2);
    cudaGetSymbolAddress((void**)&p_t2, g_t2);

    // 1: fused prep (pack Wc/bl, BN fold, zero counters, segment bounds)
    k_prep<<<512, 256>>>(Wih, Whh, bih, bhh, g1, be1, rm1, rv1, b1l,
                         g2, be2, rm2, rv2, b2l, batch);
    // 2-4: CSR build
    k_hist<<<(EE + 255) / 256, 256>>>(ei);
    k_scan<<<1, 256>>>();
    k_fill<<<(EE + 255) / 256, 256>>>(ei);

    dim3 gL((NN + 127) / 128, 2);
    // 5-6: layer 1
    k_gemm_tf32<<<gL, 256>>>(x, W1l, W1r, p_y);
    k_agg<<<(NN * 32 + 255) / 256, 256>>>(p_y, p_s1, p_t1, p_h1);
    // 7-8: layer 2
    k_gemm_tf32<<<gL, 256>>>(p_h1, W2l, W2r, p_y);
    k_agg<<<(NN * 32 + 255) / 256, 256>>>(p_y, p_s2, p_t2, p_h2);

    // 9-11: set2set, one fused kernel per step
    k_step<<<BB, 256>>>(1);
    k_step<<<BB, 256>>>(0);
    k_step<<<BB, 256>>>(0);

    // 12: final projection: out = [h|r] @ Wp^T + bp
    dim3 gf(BB / 64, 1);
    k_gemm<<<gf, 256>>>(p_A, 256, Wp, 256, bp, (float*)d_out, 128, 256);
}

// round 4
// speedup vs baseline: 2.5788x; 1.0658x over previous
#include <cuda_runtime.h>
#include <cuda_fp16.h>
#include <cstdint>

#define NN 40000
#define EE 640000
#define BB 256

// ---------------- scratch (device globals; no allocation) ----------------
__device__ __half g_yl[NN * 128];      // lin_l output (gathered) fp16
__device__ __half g_yr[NN * 128];      // lin_r output fp16
__device__ float g_h1[NN * 128];
__device__ float g_h2[NN * 128];
__device__ float g_inv[NN];
__device__ int   g_dc[2 * NN];         // deg | cursor
__device__ int   g_start[NN + 1];
__device__ int   g_csr[EE];            // src ids sorted by dst
__device__ int   g_seg[BB + 1];
__device__ float g_Wc[512 * 256];      // [Wih[:,:128]+Whh | Wih[:,128:]]
__device__ float g_bl[512];            // bih + bhh
__device__ float g_s1[128], g_t1[128], g_s2[128], g_t2[128];

// ---------------- helpers ----------------
__device__ __forceinline__ float sigmoidf_(float x) { return 1.f / (1.f + expf(-x)); }

__device__ __forceinline__ float to_tf32(float x) {
    uint32_t u;
    asm("cvt.rna.tf32.f32 %0, %1;" : "=r"(u) : "f"(x));
    return __uint_as_float(u);
}

__device__ __forceinline__ void mma_tf32(float c[4], uint32_t a0, uint32_t a1,
                                         uint32_t a2, uint32_t a3,
                                         uint32_t b0, uint32_t b1) {
    asm volatile(
        "mma.sync.aligned.m16n8k8.row.col.f32.tf32.tf32.f32 "
        "{%0,%1,%2,%3}, {%4,%5,%6,%7}, {%8,%9}, {%0,%1,%2,%3};\n"
        : "+f"(c[0]), "+f"(c[1]), "+f"(c[2]), "+f"(c[3])
        : "r"(a0), "r"(a1), "r"(a2), "r"(a3), "r"(b0), "r"(b1));
}

__device__ __forceinline__ float dot8(float4 w0, float4 w1, float4 v0, float4 v1) {
    return w0.x * v0.x + w0.y * v0.y + w0.z * v0.z + w0.w * v0.w
         + w1.x * v1.x + w1.y * v1.y + w1.z * v1.z + w1.w * v1.w;
}

// ---------------- fused prep: pack Wc/bl, fold BN, zero/seg, degree histogram ----------------
__global__ void k_prep(const float* __restrict__ Wih, const float* __restrict__ Whh,
                       const float* __restrict__ bih, const float* __restrict__ bhh,
                       const float* __restrict__ g1, const float* __restrict__ be1,
                       const float* __restrict__ rm1, const float* __restrict__ rv1,
                       const float* __restrict__ b1l,
                       const float* __restrict__ g2, const float* __restrict__ be2,
                       const float* __restrict__ rm2, const float* __restrict__ rv2,
                       const float* __restrict__ b2l,
                       const int* __restrict__ batch, const int* __restrict__ ei) {
    int i = blockIdx.x * blockDim.x + threadIdx.x;
    if (i < 512 * 256) {
        int r = i >> 8, k = i & 255;
        float w = Wih[r * 256 + k];
        if (k < 128) w += Whh[r * 128 + k];
        g_Wc[i] = w;
    }
    if (i < 512) g_bl[i] = bih[i] + bhh[i];
    if (i < 128) {
        float s = g1[i] * rsqrtf(rv1[i] + 1e-5f);
        g_s1[i] = s; g_t1[i] = be1[i] + (b1l[i] - rm1[i]) * s;
    } else if (i < 256) {
        int j = i - 128;
        float s = g2[j] * rsqrtf(rv2[j] + 1e-5f);
        g_s2[j] = s; g_t2[j] = be2[j] + (b2l[j] - rm2[j]) * s;
    }
    if (i < NN) {
        g_dc[i] = 0; g_dc[NN + i] = 0;
        int b = batch[i];
        int prev = (i == 0) ? -1 : batch[i - 1];
        for (int q = prev + 1; q <= b; q++) g_seg[q] = i;
        if (i == NN - 1)
            for (int q = b + 1; q <= BB; q++) g_seg[q] = NN;
    }
    // degree histogram must come after the zeroing above completes chip-wide;
    // grid-stride it in a second phase within the same kernel is unsafe, so
    // we rely on a separate pass below: histogram goes into g_dc via atomics
    // issued only AFTER this thread's own zero writes. Cross-block ordering is
    // handled by doing the histogram in k_hist2 logic here guarded by a
    // cooperative trick is NOT safe -> histogram moved to its own kernel? No:
    // we zero g_dc here for indices < NN, and the histogram targets the SAME
    // region. To stay safe, histogram is done in k_fillhist below.
}

__global__ void k_hist(const int* __restrict__ ei) {
    int e = blockIdx.x * blockDim.x + threadIdx.x;
    if (e < EE) atomicAdd(&g_dc[ei[EE + e]], 1);
}

__global__ void k_scan() {  // single block, 256 threads
    __shared__ int part[256];
    int tid = threadIdx.x;
    const int chunk = (NN + 255) / 256;
    int b0 = tid * chunk, b1 = min(b0 + chunk, NN);
    int s = 0;
    for (int i = b0; i < b1; i++) s += g_dc[i];
    part[tid] = s;
    __syncthreads();
    for (int off = 1; off < 256; off <<= 1) {
        int v = (tid >= off) ? part[tid - off] : 0;
        __syncthreads();
        part[tid] += v;
        __syncthreads();
    }
    int base = (tid == 0) ? 0 : part[tid - 1];
    for (int i = b0; i < b1; i++) {
        int d = g_dc[i];
        g_start[i] = base;
        g_inv[i] = 1.f / (float)max(d, 1);
        base += d;
    }
    if (tid == 255) g_start[NN] = base;
}

__global__ void k_fill(const int* __restrict__ ei) {
    int e = blockIdx.x * blockDim.x + threadIdx.x;
    if (e >= EE) return;
    int s = ei[e], d = ei[EE + e];
    int pos = g_start[d] + atomicAdd(&g_dc[NN + d], 1);
    g_csr[pos] = s;
}

// ---------------- tf32 tensor-core GEMM: Yl/Yr = A @ Wl^T / Wr^T (fp16 out) ----------------
__global__ __launch_bounds__(256) void k_gemm_tf32(
    const float* __restrict__ A,
    const float* __restrict__ Wl, const float* __restrict__ Wr,
    __half* __restrict__ Yl, __half* __restrict__ Yr) {
    __shared__ float As[32][133];   // [k][m]
    __shared__ float Bs[32][133];   // [k][n]
    const float* W = blockIdx.y ? Wr : Wl;
    __half* Y = blockIdx.y ? Yr : Yl;
    int m0 = blockIdx.x * 128;
    int tid = threadIdx.x;
    int warp = tid >> 5, lane = tid & 31;
    int wm = warp >> 1, wn = warp & 1;
    int gid = lane >> 2, tig = lane & 3;

    float acc[2][8][4];
#pragma unroll
    for (int i = 0; i < 2; i++)
#pragma unroll
        for (int j = 0; j < 8; j++)
#pragma unroll
            for (int q = 0; q < 4; q++) acc[i][j][q] = 0.f;

    int lrow = tid >> 3;
    int lk4 = (tid & 7) * 4;

    for (int kc = 0; kc < 128; kc += 32) {
#pragma unroll
        for (int i = 0; i < 4; i++) {
            int r = m0 + lrow + 32 * i;
            int rc = min(r, NN - 1);
            float4 v = *(const float4*)(A + (size_t)rc * 128 + kc + lk4);
            As[lk4 + 0][lrow + 32 * i] = to_tf32(v.x);
            As[lk4 + 1][lrow + 32 * i] = to_tf32(v.y);
            As[lk4 + 2][lrow + 32 * i] = to_tf32(v.z);
            As[lk4 + 3][lrow + 32 * i] = to_tf32(v.w);
            float4 w = *(const float4*)(W + (size_t)(lrow + 32 * i) * 128 + kc + lk4);
            Bs[lk4 + 0][lrow + 32 * i] = to_tf32(w.x);
            Bs[lk4 + 1][lrow + 32 * i] = to_tf32(w.y);
            Bs[lk4 + 2][lrow + 32 * i] = to_tf32(w.z);
            Bs[lk4 + 3][lrow + 32 * i] = to_tf32(w.w);
        }
        __syncthreads();
#pragma unroll
        for (int ks = 0; ks < 32; ks += 8) {
            uint32_t a[2][4];
#pragma unroll
            for (int mt = 0; mt < 2; mt++) {
                int mb = wm * 32 + mt * 16;
                a[mt][0] = __float_as_uint(As[ks + tig][mb + gid]);
                a[mt][1] = __float_as_uint(As[ks + tig][mb + gid + 8]);
                a[mt][2] = __float_as_uint(As[ks + tig + 4][mb + gid]);
                a[mt][3] = __float_as_uint(As[ks + tig + 4][mb + gid + 8]);
            }
#pragma unroll
            for (int nt = 0; nt < 8; nt++) {
                int nb = wn * 64 + nt * 8;
                uint32_t b0 = __float_as_uint(Bs[ks + tig][nb + gid]);
                uint32_t b1 = __float_as_uint(Bs[ks + tig + 4][nb + gid]);
                mma_tf32(acc[0][nt], a[0][0], a[0][1], a[0][2], a[0][3], b0, b1);
                mma_tf32(acc[1][nt], a[1][0], a[1][1], a[1][2], a[1][3], b0, b1);
            }
        }
        __syncthreads();
    }

    int ncol0 = wn * 64;
#pragma unroll
    for (int mt = 0; mt < 2; mt++) {
        int row0 = m0 + wm * 32 + mt * 16 + gid;
        int row1 = row0 + 8;
#pragma unroll
        for (int nt = 0; nt < 8; nt++) {
            int c = ncol0 + nt * 8 + tig * 2;
            if (row0 < NN)
                *(__half2*)(Y + (size_t)row0 * 128 + c) =
                    __floats2half2_rn(acc[mt][nt][0], acc[mt][nt][1]);
            if (row1 < NN)
                *(__half2*)(Y + (size_t)row1 * 128 + c) =
                    __floats2half2_rn(acc[mt][nt][2], acc[mt][nt][3]);
        }
    }
}

// ---------------- CSR aggregation + epilogue (fp16 gather, fp32 accum) ----------------
__global__ void k_agg(const float* __restrict__ s, const float* __restrict__ t,
                      float* __restrict__ out) {
    int gt = blockIdx.x * blockDim.x + threadIdx.x;
    int w = gt >> 5;
    if (w >= NN) return;
    int lane = gt & 31;
    int e0 = g_start[w], e1 = g_start[w + 1];
    float4 acc0 = make_float4(0.f, 0.f, 0.f, 0.f);
    float4 acc1 = make_float4(0.f, 0.f, 0.f, 0.f);
    const uint2* Yl2 = (const uint2*)g_yl;   // 4 halves per uint2, row = 32 uint2
    int e = e0;
    for (; e + 2 <= e1; e += 2) {
        int sa = __ldg(g_csr + e);
        int sb = __ldg(g_csr + e + 1);
        uint2 ua = Yl2[(size_t)sa * 32 + lane];
        uint2 ub = Yl2[(size_t)sb * 32 + lane];
        float2 a0 = __half22float2(*(__half2*)&ua.x);
        float2 a1 = __half22float2(*(__half2*)&ua.y);
        float2 b0 = __half22float2(*(__half2*)&ub.x);
        float2 b1 = __half22float2(*(__half2*)&ub.y);
        acc0.x += a0.x; acc0.y += a0.y; acc0.z += a1.x; acc0.w += a1.y;
        acc1.x += b0.x; acc1.y += b0.y; acc1.z += b1.x; acc1.w += b1.y;
    }
    if (e < e1) {
        int sa = __ldg(g_csr + e);
        uint2 ua = Yl2[(size_t)sa * 32 + lane];
        float2 a0 = __half22float2(*(__half2*)&ua.x);
        float2 a1 = __half22float2(*(__half2*)&ua.y);
        acc0.x += a0.x; acc0.y += a0.y; acc0.z += a1.x; acc0.w += a1.y;
    }
    acc0.x += acc1.x; acc0.y += acc1.y; acc0.z += acc1.z; acc0.w += acc1.w;
    float iv = g_inv[w];
    uint2 ur = ((const uint2*)g_yr)[(size_t)w * 32 + lane];
    float2 r0 = __half22float2(*(__half2*)&ur.x);
    float2 r1 = __half22float2(*(__half2*)&ur.y);
    float4 sv = ((const float4*)s)[lane];
    float4 tv = ((const float4*)t)[lane];
    float4 o;
    o.x = fmaxf(fmaf(fmaf(acc0.x, iv, r0.x), sv.x, tv.x), 0.f);
    o.y = fmaxf(fmaf(fmaf(acc0.y, iv, r0.y), sv.y, tv.y), 0.f);
    o.z = fmaxf(fmaf(fmaf(acc0.z, iv, r1.x), sv.z, tv.z), 0.f);
    o.w = fmaxf(fmaf(fmaf(acc0.w, iv, r1.y), sv.w, tv.w), 0.f);
    ((float4*)out)[(size_t)w * 32 + lane] = o;
}

// ---------------- fully fused set2set (3 steps) + final projection ----------------
// 128 blocks x 256 threads; each block owns graphs 2b and 2b+1.
// Gate dots: 8 warps x 64 rows, each weight row serves BOTH graphs.
// Attention: warps 0-3 -> graph A, warps 4-7 -> graph B.
__global__ __launch_bounds__(256) void k_s2s(const float* __restrict__ Wp,
                                             const float* __restrict__ bp,
                                             float* __restrict__ out) {
    int blk = blockIdx.x;
    int tid = threadIdx.x;
    int warp = tid >> 5, lane = tid & 31;
    int gr = warp >> 2;              // graph slot (0/1) for attention/projection
    int wl = warp & 3;               // warp-local index within graph
    int g = blk * 2 + gr;

    __shared__ float sh_v[2][256];       // q_star = [q | r]
    __shared__ float sh_q[2][128];
    __shared__ float sh_c[2][128];
    __shared__ float sh_gates[2][512];
    __shared__ float sh_r[2][4][128];
    __shared__ float sh_s[2][8];         // [graph][0..3 = max, 4..7 = sum]

    if (tid < 128) { sh_c[0][tid] = 0.f; sh_c[1][tid] = 0.f; }
    __syncthreads();

    int s0 = g_seg[g], s1 = g_seg[g + 1];
    const float4* H4 = (const float4*)g_h2;

    for (int step = 0; step < 3; step++) {
        // ---- gates ----
        if (step == 0) {
            float b0 = g_bl[tid], b1 = g_bl[256 + tid];
            sh_gates[0][tid] = b0; sh_gates[0][256 + tid] = b1;
            sh_gates[1][tid] = b0; sh_gates[1][256 + tid] = b1;
        } else {
            const float4* VA = (const float4*)sh_v[0];
            const float4* VB = (const float4*)sh_v[1];
            float4 va0 = VA[lane], va1 = VA[32 + lane];
            float4 vb0 = VB[lane], vb1 = VB[32 + lane];
#pragma unroll 4
            for (int j = 0; j < 64; j++) {
                int r = warp * 64 + j;
                const float4* Wr4 = (const float4*)(g_Wc + (size_t)r * 256);
                float4 w0 = Wr4[lane], w1 = Wr4[32 + lane];
                float pA = dot8(w0, w1, va0, va1);
                float pB = dot8(w0, w1, vb0, vb1);
#pragma unroll
                for (int o = 16; o > 0; o >>= 1) {
                    pA += __shfl_xor_sync(0xffffffffu, pA, o);
                    pB += __shfl_xor_sync(0xffffffffu, pB, o);
                }
                if (lane == 0) {
                    float bb = g_bl[r];
                    sh_gates[0][r] = pA + bb;
                    sh_gates[1][r] = pB + bb;
                }
            }
        }
        __syncthreads();

        // ---- LSTM cell (256 threads = 2 graphs x 128 dims) ----
        {
            int gg = tid >> 7, d = tid & 127;
            float ig = sh_gates[gg][d], fg = sh_gates[gg][128 + d];
            float gv = sh_gates[gg][256 + d], og = sh_gates[gg][384 + d];
            float c0 = sh_c[gg][d];
            float cn = sigmoidf_(fg) * c0 + sigmoidf_(ig) * tanhf(gv);
            float hn = sigmoidf_(og) * tanhf(cn);
            sh_c[gg][d] = cn;
            sh_q[gg][d] = hn;
        }
        __syncthreads();

        // ---- attention pass 1: segment max ----
        float4 qv = ((const float4*)sh_q[gr])[lane];
        float wmax = -3.402823466e38f;
        for (int n = s0 + wl; n < s1; n += 4) {
            float4 hv = H4[(size_t)n * 32 + lane];
            float p = hv.x * qv.x + hv.y * qv.y + hv.z * qv.z + hv.w * qv.w;
#pragma unroll
            for (int o = 16; o > 0; o >>= 1) p += __shfl_xor_sync(0xffffffffu, p, o);
            wmax = fmaxf(wmax, p);
        }
        if (lane == 0) sh_s[gr][wl] = wmax;
        __syncthreads();
        float emax = fmaxf(fmaxf(sh_s[gr][0], sh_s[gr][1]),
                           fmaxf(sh_s[gr][2], sh_s[gr][3]));

        // ---- attention pass 2: exp-sum + weighted feature sum ----
        float asum = 0.f;
        float4 racc = make_float4(0.f, 0.f, 0.f, 0.f);
        for (int n = s0 + wl; n < s1; n += 4) {
            float4 hv = H4[(size_t)n * 32 + lane];
            float p = hv.x * qv.x + hv.y * qv.y + hv.z * qv.z + hv.w * qv.w;
#pragma unroll
            for (int o = 16; o > 0; o >>= 1) p += __shfl_xor_sync(0xffffffffu, p, o);
            float a = expf(p - emax);
            asum += a;
            racc.x += a * hv.x; racc.y += a * hv.y; racc.z += a * hv.z; racc.w += a * hv.w;
        }
        ((float4*)sh_r[gr][wl])[lane] = racc;
        if (lane == 0) sh_s[gr][4 + wl] = asum;
        __syncthreads();

        // ---- combine: q_star = [q | r] ----
        {
            int gg = tid >> 7, d = tid & 127;
            float den = sh_s[gg][4] + sh_s[gg][5] + sh_s[gg][6] + sh_s[gg][7];
            float rsum = sh_r[gg][0][d] + sh_r[gg][1][d] + sh_r[gg][2][d] + sh_r[gg][3][d];
            float r = (den > 0.f) ? rsum / den : 0.f;
            sh_v[gg][d] = sh_q[gg][d];
            sh_v[gg][128 + d] = r;
        }
        __syncthreads();
    }

    // ---- final projection: out[g] = q_star @ Wp^T + bp ----
    const float4* V = (const float4*)sh_v[gr];
    float4 v0 = V[lane], v1 = V[32 + lane];
#pragma unroll 4
    for (int j = 0; j < 32; j++) {
        int row = wl * 32 + j;
        const float4* Wr4 = (const float4*)(Wp + (size_t)row * 256);
        float4 w0 = Wr4[lane], w1 = Wr4[32 + lane];
        float p = dot8(w0, w1, v0, v1);
#pragma unroll
        for (int o = 16; o > 0; o >>= 1) p += __shfl_xor_sync(0xffffffffu, p, o);
        if (lane == 0) out[g * 128 + row] = p + bp[row];
    }
}

// ---------------- host ----------------
extern "C" void kernel_launch(void* const* d_in, const int* in_sizes, int n_in,
                              void* d_out, int out_size) {
    const float* x    = (const float*)d_in[0];
    const int*   ei   = (const int*)d_in[1];
    const int*   batch= (const int*)d_in[2];
    const float* W1l  = (const float*)d_in[3];
    const float* b1l  = (const float*)d_in[4];
    const float* W1r  = (const float*)d_in[5];
    const float* g1   = (const float*)d_in[6];
    const float* be1  = (const float*)d_in[7];
    const float* rm1  = (const float*)d_in[8];
    const float* rv1  = (const float*)d_in[9];
    const float* W2l  = (const float*)d_in[10];
    const float* b2l  = (const float*)d_in[11];
    const float* W2r  = (const float*)d_in[12];
    const float* g2   = (const float*)d_in[13];
    const float* be2  = (const float*)d_in[14];
    const float* rm2  = (const float*)d_in[15];
    const float* rv2  = (const float*)d_in[16];
    const float* Wih  = (const float*)d_in[17];
    const float* Whh  = (const float*)d_in[18];
    const float* bih  = (const float*)d_in[19];
    const float* bhh  = (const float*)d_in[20];
    const float* Wp   = (const float*)d_in[21];
    const float* bp   = (const float*)d_in[22];

    __half *p_yl, *p_yr;
    float *p_h1, *p_h2, *p_s1, *p_t1, *p_s2, *p_t2;
    cudaGetSymbolAddress((void**)&p_yl, g_yl);
    cudaGetSymbolAddress((void**)&p_yr, g_yr);
    cudaGetSymbolAddress((void**)&p_h1, g_h1);
    cudaGetSymbolAddress((void**)&p_h2, g_h2);
    cudaGetSymbolAddress((void**)&p_s1, g_s1);
    cudaGetSymbolAddress((void**)&p_t1, g_t1);
    cudaGetSymbolAddress((void**)&p_s2, g_s2);
    cudaGetSymbolAddress((void**)&p_t2, g_t2);

    // 1: fused prep (pack Wc/bl, BN fold, zero counters, segment bounds)
    k_prep<<<512, 256>>>(Wih, Whh, bih, bhh, g1, be1, rm1, rv1, b1l,
                         g2, be2, rm2, rv2, b2l, batch, ei);
    // 2-4: CSR build
    k_hist<<<(EE + 255) / 256, 256>>>(ei);
    k_scan<<<1, 256>>>();
    k_fill<<<(EE + 255) / 256, 256>>>(ei);

    dim3 gL((NN + 127) / 128, 2);
    // 5-6: layer 1
    k_gemm_tf32<<<gL, 256>>>(x, W1l, W1r, p_yl, p_yr);
    k_agg<<<(NN * 32 + 255) / 256, 256>>>(p_s1, p_t1, p_h1);
    // 7-8: layer 2
    k_gemm_tf32<<<gL, 256>>>(p_h1, W2l, W2r, p_yl, p_yr);
    k_agg<<<(NN * 32 + 255) / 256, 256>>>(p_s2, p_t2, p_h2);

    // 9: fused set2set (3 steps) + final projection -> d_out
    k_s2s<<<BB / 2, 256>>>(Wp, bp, (float*)d_out);
}